// round 2
// baseline (speedup 1.0000x reference)
#include <cuda_runtime.h>
#include <cstdint>

// VoxelHashTable: for each query point p (M x 3 f32):
//   grid = floor(p / 0.1)  (int64)
//   h = (grid . primes) mod 2^20       (products overflow int32 -> compute in 64-bit)
//   v = buffer_voxel_index[h]          (stored as int32 by the harness)
//   out[row] = (0 <= v < total_voxels) ? voxel_features[v] : 0    (768 f32)
//
// Pure gather + streaming copy; HBM-bound (~1.6 GB traffic).
// One block per query, 192 threads, one float4 per thread (192*16B = 3KB row).

#define FEATURE_DIM 768
#define VEC4_PER_ROW (FEATURE_DIM / 4)   // 192
#define TABLE_MASK ((1u << 20) - 1u)

__global__ void __launch_bounds__(VEC4_PER_ROW) voxel_hash_gather(
    const float* __restrict__ query_pts,        // [M, 3]
    const float4* __restrict__ voxel_features,  // [total_voxels, 192] as float4
    const int* __restrict__ buf,                // [2^20], int32
    float4* __restrict__ out,                   // [M, 192] as float4
    int total_voxels)
{
    const int qi = blockIdx.x;
    const int t  = threadIdx.x;   // 0..191

    // Broadcast loads (all threads in the block hit the same 3 words).
    const float px = __ldg(&query_pts[qi * 3 + 0]);
    const float py = __ldg(&query_pts[qi * 3 + 1]);
    const float pz = __ldg(&query_pts[qi * 3 + 2]);

    // Must be f32 division by 0.1f to match jnp.floor(q / RES) bitwise.
    const long long gx = (long long)floorf(px / 0.1f);
    const long long gy = (long long)floorf(py / 0.1f);
    const long long gz = (long long)floorf(pz / 0.1f);

    // Power-of-two modulus: two's-complement AND == Python mod, incl. negatives.
    // Products are ~1e10, so 64-bit arithmetic is required (matches int64 ref).
    const unsigned h = (unsigned)((gx * 73856093LL + gy * 19349669LL
                                   + gz * 83492791LL) & (long long)TABLE_MASK);

    const int v = __ldg(&buf[h]);

    float4* o = out + (size_t)qi * VEC4_PER_ROW + t;
    if (v >= 0 && v < total_voxels) {
        *o = __ldg(voxel_features + (size_t)v * VEC4_PER_ROW + t);
    } else {
        *o = make_float4(0.f, 0.f, 0.f, 0.f);
    }
}

extern "C" void kernel_launch(void* const* d_in, const int* in_sizes, int n_in,
                              void* d_out, int out_size)
{
    const float*  query_pts = (const float*)d_in[0];
    const float4* feats     = (const float4*)d_in[1];
    const int*    buf       = (const int*)d_in[2];
    float4*       out       = (float4*)d_out;

    const int M = in_sizes[0] / 3;                 // 262144
    const int total_voxels = in_sizes[1] / FEATURE_DIM;

    voxel_hash_gather<<<M, VEC4_PER_ROW>>>(query_pts, feats, buf, out, total_voxels);
}

// round 3
// speedup vs baseline: 1.5688x; 1.5688x over previous
#include <cuda_runtime.h>
#include <cstdint>

// VoxelHashTable — warp-per-query version.
//   grid = floor(p / 0.1f)             (f32 divide, bit-exact vs jnp)
//   h = (grid . primes) & (2^20 - 1)   (64-bit products; int32 table entries)
//   out[row] = valid ? voxel_features[v] : 0   (768 f32 = 3KB)
//
// One warp copies one row: 6 independent float4 loads per lane issued
// back-to-back (MLP=6) to put ~6x more bytes in flight than the
// thread-per-float4 version (which measured latency-bound at 4.1 TB/s).

#define FEATURE_DIM 768
#define VEC4_PER_ROW (FEATURE_DIM / 4)     // 192
#define V4_PER_LANE (VEC4_PER_ROW / 32)    // 6
#define TABLE_MASK ((1u << 20) - 1u)
#define THREADS 256                        // 8 warps = 8 queries / block

__global__ void __launch_bounds__(THREADS) voxel_hash_gather_warp(
    const float* __restrict__ query_pts,        // [M, 3]
    const float4* __restrict__ voxel_features,  // [total_voxels, 192] as float4
    const int* __restrict__ buf,                // [2^20], int32
    float4* __restrict__ out,                   // [M, 192] as float4
    int total_voxels)
{
    const int warp = threadIdx.x >> 5;
    const int lane = threadIdx.x & 31;
    const int qi   = blockIdx.x * (THREADS / 32) + warp;

    // Broadcast loads: all lanes hit the same 3 words (single L1 transaction).
    const float px = __ldg(&query_pts[qi * 3 + 0]);
    const float py = __ldg(&query_pts[qi * 3 + 1]);
    const float pz = __ldg(&query_pts[qi * 3 + 2]);

    // f32 division by 0.1f required for bit-exact floor(q / RES).
    const long long gx = (long long)floorf(px / 0.1f);
    const long long gy = (long long)floorf(py / 0.1f);
    const long long gz = (long long)floorf(pz / 0.1f);

    // Products ~1e10 overflow int32 -> 64-bit math. Power-of-two mod == AND.
    const unsigned h = (unsigned)((gx * 73856093LL + gy * 19349669LL
                                   + gz * 83492791LL) & (long long)TABLE_MASK);

    const int v = __ldg(&buf[h]);
    const bool valid = (v >= 0 && v < total_voxels);

    const float4* src = voxel_features + (size_t)v * VEC4_PER_ROW + lane;
    float4*       dst = out            + (size_t)qi * VEC4_PER_ROW + lane;

    float4 r[V4_PER_LANE];
    if (valid) {
        // 6 independent 128-bit loads, issued back-to-back (MLP = 6).
        #pragma unroll
        for (int i = 0; i < V4_PER_LANE; i++)
            r[i] = __ldg(src + 32 * i);
    } else {
        #pragma unroll
        for (int i = 0; i < V4_PER_LANE; i++)
            r[i] = make_float4(0.f, 0.f, 0.f, 0.f);
    }

    #pragma unroll
    for (int i = 0; i < V4_PER_LANE; i++)
        dst[32 * i] = r[i];
}

extern "C" void kernel_launch(void* const* d_in, const int* in_sizes, int n_in,
                              void* d_out, int out_size)
{
    const float*  query_pts = (const float*)d_in[0];
    const float4* feats     = (const float4*)d_in[1];
    const int*    buf       = (const int*)d_in[2];
    float4*       out       = (float4*)d_out;

    const int M = in_sizes[0] / 3;                  // 262144
    const int total_voxels = in_sizes[1] / FEATURE_DIM;

    const int queries_per_block = THREADS / 32;     // 8
    voxel_hash_gather_warp<<<M / queries_per_block, THREADS>>>(
        query_pts, feats, buf, out, total_voxels);
}

// round 4
// speedup vs baseline: 1.5889x; 1.0128x over previous
#include <cuda_runtime.h>
#include <cstdint>

// VoxelHashTable — two-phase version.
// Phase 1 (tiny): hash all M queries -> vidx[] (int32, __device__ scratch).
//   Removes the query-load -> hash -> table-load dependent chain from the
//   bandwidth-critical kernel.
// Phase 2 (heavy): warp-per-row gather, 6 independent float4 loads per lane,
//   streaming stores (__stcs) so the write-only 805MB output doesn't evict
//   feature rows from L2 (dup reads ~35% of queries benefit).

#define FEATURE_DIM 768
#define VEC4_PER_ROW (FEATURE_DIM / 4)     // 192
#define V4_PER_LANE (VEC4_PER_ROW / 32)    // 6
#define TABLE_MASK ((1u << 20) - 1u)
#define THREADS 256
#define M_MAX (1 << 18)                    // 262144 queries

__device__ int g_vidx[M_MAX];

__global__ void __launch_bounds__(256) hash_phase(
    const float* __restrict__ query_pts,   // [M, 3]
    const int* __restrict__ buf,           // [2^20], int32
    int M, int total_voxels)
{
    const int qi = blockIdx.x * blockDim.x + threadIdx.x;
    if (qi >= M) return;

    const float px = __ldg(&query_pts[qi * 3 + 0]);
    const float py = __ldg(&query_pts[qi * 3 + 1]);
    const float pz = __ldg(&query_pts[qi * 3 + 2]);

    // f32 division by 0.1f required for bit-exact floor(q / RES).
    const long long gx = (long long)floorf(px / 0.1f);
    const long long gy = (long long)floorf(py / 0.1f);
    const long long gz = (long long)floorf(pz / 0.1f);

    // Products ~1e10 overflow int32 -> 64-bit math. Pow2 mod == AND (neg-safe).
    const unsigned h = (unsigned)((gx * 73856093LL + gy * 19349669LL
                                   + gz * 83492791LL) & (long long)TABLE_MASK);

    int v = __ldg(&buf[h]);
    if (v >= total_voxels) v = -1;   // fold bounds check into the index
    g_vidx[qi] = v;
}

__global__ void __launch_bounds__(THREADS) gather_phase(
    const float4* __restrict__ voxel_features,  // [total_voxels, 192] as float4
    float4* __restrict__ out)                   // [M, 192] as float4
{
    const int warp = threadIdx.x >> 5;
    const int lane = threadIdx.x & 31;
    const int qi   = blockIdx.x * (THREADS / 32) + warp;

    const int v = __ldg(&g_vidx[qi]);   // L2-resident (1MB), broadcast in warp

    const float4* src = voxel_features + (size_t)v * VEC4_PER_ROW + lane;
    float4*       dst = out            + (size_t)qi * VEC4_PER_ROW + lane;

    float4 r[V4_PER_LANE];
    if (v >= 0) {
        #pragma unroll
        for (int i = 0; i < V4_PER_LANE; i++)   // 6 loads in flight (MLP=6)
            r[i] = __ldg(src + 32 * i);
    } else {
        #pragma unroll
        for (int i = 0; i < V4_PER_LANE; i++)
            r[i] = make_float4(0.f, 0.f, 0.f, 0.f);
    }

    // Streaming stores: output is never re-read; keep L2 for feature rows.
    #pragma unroll
    for (int i = 0; i < V4_PER_LANE; i++)
        __stcs(dst + 32 * i, r[i]);
}

extern "C" void kernel_launch(void* const* d_in, const int* in_sizes, int n_in,
                              void* d_out, int out_size)
{
    const float*  query_pts = (const float*)d_in[0];
    const float4* feats     = (const float4*)d_in[1];
    const int*    buf       = (const int*)d_in[2];
    float4*       out       = (float4*)d_out;

    const int M = in_sizes[0] / 3;                  // 262144
    const int total_voxels = in_sizes[1] / FEATURE_DIM;

    hash_phase<<<(M + 255) / 256, 256>>>(query_pts, buf, M, total_voxels);

    const int queries_per_block = THREADS / 32;     // 8
    gather_phase<<<M / queries_per_block, THREADS>>>(feats, out);
}

// round 5
// speedup vs baseline: 1.6233x; 1.0216x over previous
#include <cuda_runtime.h>
#include <cstdint>

// VoxelHashTable — counting-sort-clustered gather.
// ~35% of queries hit duplicate voxel rows (278MB of dup DRAM reads when
// scattered). Bucket queries by vidx>>7 so duplicate/nearby rows are read
// within a short time window -> served from L2 instead of DRAM.
//
// Pipeline (all __device__ scratch, graph-capturable, deterministic output):
//   1. zero histogram
//   2. hash queries -> vidx[], histogram buckets
//   3. one-block exclusive scan over 8192 bins
//   4. scatter query ids -> perm[] (atomic bucket offsets)
//   5. gather in perm order: warp-per-row, 6 independent float4 loads (MLP=6)

#define FEATURE_DIM 768
#define VEC4_PER_ROW (FEATURE_DIM / 4)     // 192
#define V4_PER_LANE (VEC4_PER_ROW / 32)    // 6
#define TABLE_MASK ((1u << 20) - 1u)
#define THREADS 256
#define M_MAX (1 << 18)                    // 262144 queries
#define BUCKET_SHIFT 7                     // 128 voxel rows per bucket
#define NBINS 8192                         // covers total_voxels up to 2^20

__device__ int g_vidx[M_MAX];
__device__ int g_perm[M_MAX];
__device__ int g_hist[NBINS];
__device__ int g_off[NBINS];

__global__ void zero_hist()
{
    g_hist[blockIdx.x * blockDim.x + threadIdx.x] = 0;
}

__global__ void __launch_bounds__(256) hash_hist(
    const float* __restrict__ query_pts,   // [M, 3]
    const int* __restrict__ buf,           // [2^20], int32
    int M, int total_voxels)
{
    const int qi = blockIdx.x * blockDim.x + threadIdx.x;
    if (qi >= M) return;

    const float px = __ldg(&query_pts[qi * 3 + 0]);
    const float py = __ldg(&query_pts[qi * 3 + 1]);
    const float pz = __ldg(&query_pts[qi * 3 + 2]);

    // f32 division by 0.1f required for bit-exact floor(q / RES).
    const long long gx = (long long)floorf(px / 0.1f);
    const long long gy = (long long)floorf(py / 0.1f);
    const long long gz = (long long)floorf(pz / 0.1f);

    // Products ~1e10 overflow int32 -> 64-bit math. Pow2 mod == AND (neg-safe).
    const unsigned h = (unsigned)((gx * 73856093LL + gy * 19349669LL
                                   + gz * 83492791LL) & (long long)TABLE_MASK);

    int v = __ldg(&buf[h]);
    if (v >= total_voxels) v = -1;
    g_vidx[qi] = v;

    const int b = (v >= 0) ? (v >> BUCKET_SHIFT) : (NBINS - 1);
    atomicAdd(&g_hist[b], 1);
}

// Exclusive prefix sum over NBINS=8192 bins, single block of 1024 threads.
__global__ void __launch_bounds__(1024) scan_hist()
{
    const int tid  = threadIdx.x;
    const int lane = tid & 31;
    const int warp = tid >> 5;

    int v[NBINS / 1024];                 // 8 per thread
    int sum = 0;
    #pragma unroll
    for (int i = 0; i < NBINS / 1024; i++) {
        v[i] = g_hist[tid * (NBINS / 1024) + i];
        sum += v[i];
    }

    // inclusive warp scan of per-thread sums
    int x = sum;
    #pragma unroll
    for (int d = 1; d < 32; d <<= 1) {
        int y = __shfl_up_sync(0xFFFFFFFFu, x, d);
        if (lane >= d) x += y;
    }

    __shared__ int wsum[32];
    if (lane == 31) wsum[warp] = x;
    __syncthreads();
    if (warp == 0) {
        int w = wsum[lane];
        #pragma unroll
        for (int d = 1; d < 32; d <<= 1) {
            int y = __shfl_up_sync(0xFFFFFFFFu, w, d);
            if (lane >= d) w += y;
        }
        wsum[lane] = w;
    }
    __syncthreads();

    int excl = x - sum + (warp > 0 ? wsum[warp - 1] : 0);
    #pragma unroll
    for (int i = 0; i < NBINS / 1024; i++) {
        g_off[tid * (NBINS / 1024) + i] = excl;
        excl += v[i];
    }
}

__global__ void __launch_bounds__(256) scatter_perm(int M)
{
    const int qi = blockIdx.x * blockDim.x + threadIdx.x;
    if (qi >= M) return;
    const int v = g_vidx[qi];
    const int b = (v >= 0) ? (v >> BUCKET_SHIFT) : (NBINS - 1);
    const int pos = atomicAdd(&g_off[b], 1);
    g_perm[pos] = qi;
}

__global__ void __launch_bounds__(THREADS) gather_phase(
    const float4* __restrict__ voxel_features,  // [total_voxels, 192] as float4
    float4* __restrict__ out)                   // [M, 192] as float4
{
    const int warp = threadIdx.x >> 5;
    const int lane = threadIdx.x & 31;
    const int wi   = blockIdx.x * (THREADS / 32) + warp;

    const int qi = __ldg(&g_perm[wi]);   // L2-resident, warp-broadcast
    const int v  = __ldg(&g_vidx[qi]);

    const float4* src = voxel_features + (size_t)v * VEC4_PER_ROW + lane;
    float4*       dst = out            + (size_t)qi * VEC4_PER_ROW + lane;

    float4 r[V4_PER_LANE];
    if (v >= 0) {
        #pragma unroll
        for (int i = 0; i < V4_PER_LANE; i++)   // 6 loads in flight (MLP=6)
            r[i] = __ldg(src + 32 * i);
    } else {
        #pragma unroll
        for (int i = 0; i < V4_PER_LANE; i++)
            r[i] = make_float4(0.f, 0.f, 0.f, 0.f);
    }

    // Streaming stores: output never re-read; keep L2 for feature rows.
    #pragma unroll
    for (int i = 0; i < V4_PER_LANE; i++)
        __stcs(dst + 32 * i, r[i]);
}

extern "C" void kernel_launch(void* const* d_in, const int* in_sizes, int n_in,
                              void* d_out, int out_size)
{
    const float*  query_pts = (const float*)d_in[0];
    const float4* feats     = (const float4*)d_in[1];
    const int*    buf       = (const int*)d_in[2];
    float4*       out       = (float4*)d_out;

    const int M = in_sizes[0] / 3;                  // 262144
    const int total_voxels = in_sizes[1] / FEATURE_DIM;

    zero_hist<<<NBINS / 1024, 1024>>>();
    hash_hist<<<(M + 255) / 256, 256>>>(query_pts, buf, M, total_voxels);
    scan_hist<<<1, 1024>>>();
    scatter_perm<<<(M + 255) / 256, 256>>>(M);

    gather_phase<<<M / (THREADS / 32), THREADS>>>(feats, out);
}

// round 6
// speedup vs baseline: 1.7032x; 1.0492x over previous
#include <cuda_runtime.h>
#include <cstdint>

// VoxelHashTable — counting-sort-clustered gather, cheap pre-pass edition.
// Gather (at HBM roofline): queries sorted by vidx>>7 so duplicate/nearby
// feature rows hit L2 (dedups ~278MB of DRAM reads).
// Pre-pass made cheap:
//   - rank-within-bin captured from hash_hist's atomicAdd return value,
//     so scatter needs NO atomics (pos = off[bin] + rank)
//   - 4 queries per thread in hash/scatter (MLP=4, they were latency-bound)

#define FEATURE_DIM 768
#define VEC4_PER_ROW (FEATURE_DIM / 4)     // 192
#define V4_PER_LANE (VEC4_PER_ROW / 32)    // 6
#define TABLE_MASK ((1u << 20) - 1u)
#define THREADS 256
#define M_MAX (1 << 18)                    // 262144 queries
#define BUCKET_SHIFT 7                     // 128 voxel rows per bucket
#define NBINS 8192

__device__ int g_vidx[M_MAX];
__device__ int g_rank[M_MAX];
__device__ int g_perm[M_MAX];
__device__ int g_hist[NBINS];
__device__ int g_off[NBINS];

__global__ void zero_hist()
{
    g_hist[blockIdx.x * blockDim.x + threadIdx.x] = 0;
}

// 4 queries per thread: hash, table lookup, bin rank via atomicAdd return.
__global__ void __launch_bounds__(256) hash_hist(
    const float* __restrict__ query_pts,   // [M, 3]
    const int* __restrict__ buf,           // [2^20], int32
    int total_voxels)
{
    const int t   = blockIdx.x * blockDim.x + threadIdx.x;
    const int qi0 = t * 4;

    // 4 points = 12 floats = 3 aligned float4 loads (qi0 % 4 == 0).
    const float4* qp = (const float4*)(query_pts + qi0 * 3);
    const float4 a = __ldg(qp + 0);
    const float4 b = __ldg(qp + 1);
    const float4 c = __ldg(qp + 2);
    const float px[4] = {a.x, a.w, b.z, c.y};
    const float py[4] = {a.y, b.x, b.w, c.z};
    const float pz[4] = {a.z, b.y, c.x, c.w};

    unsigned h[4];
    #pragma unroll
    for (int i = 0; i < 4; i++) {
        // f32 division by 0.1f required for bit-exact floor(q / RES).
        const long long gx = (long long)floorf(px[i] / 0.1f);
        const long long gy = (long long)floorf(py[i] / 0.1f);
        const long long gz = (long long)floorf(pz[i] / 0.1f);
        // Products ~1e10 overflow int32 -> 64-bit. Pow2 mod == AND (neg-safe).
        h[i] = (unsigned)((gx * 73856093LL + gy * 19349669LL
                           + gz * 83492791LL) & (long long)TABLE_MASK);
    }

    int v[4];
    #pragma unroll
    for (int i = 0; i < 4; i++)            // 4 independent table loads
        v[i] = __ldg(&buf[h[i]]);

    int4 vv, rr;
    int* vp = &vv.x;
    int* rp = &rr.x;
    #pragma unroll
    for (int i = 0; i < 4; i++) {
        int vi = (v[i] < total_voxels) ? v[i] : -1;
        const int bin = (vi >= 0) ? (vi >> BUCKET_SHIFT) : (NBINS - 1);
        vp[i] = vi;
        rp[i] = atomicAdd(&g_hist[bin], 1);   // rank within bin
    }

    *(int4*)(g_vidx + qi0) = vv;
    *(int4*)(g_rank + qi0) = rr;
}

// Exclusive prefix sum over NBINS=8192 bins -> g_off. Single 1024-thread block.
__global__ void __launch_bounds__(1024) scan_hist()
{
    const int tid  = threadIdx.x;
    const int lane = tid & 31;
    const int warp = tid >> 5;

    int v[NBINS / 1024];
    int sum = 0;
    #pragma unroll
    for (int i = 0; i < NBINS / 1024; i++) {
        v[i] = g_hist[tid * (NBINS / 1024) + i];
        sum += v[i];
    }

    int x = sum;
    #pragma unroll
    for (int d = 1; d < 32; d <<= 1) {
        int y = __shfl_up_sync(0xFFFFFFFFu, x, d);
        if (lane >= d) x += y;
    }

    __shared__ int wsum[32];
    if (lane == 31) wsum[warp] = x;
    __syncthreads();
    if (warp == 0) {
        int w = wsum[lane];
        #pragma unroll
        for (int d = 1; d < 32; d <<= 1) {
            int y = __shfl_up_sync(0xFFFFFFFFu, w, d);
            if (lane >= d) w += y;
        }
        wsum[lane] = w;
    }
    __syncthreads();

    int excl = x - sum + (warp > 0 ? wsum[warp - 1] : 0);
    #pragma unroll
    for (int i = 0; i < NBINS / 1024; i++) {
        g_off[tid * (NBINS / 1024) + i] = excl;
        excl += v[i];
    }
}

// Atomic-free scatter: pos = off[bin] + rank. 4 queries per thread.
__global__ void __launch_bounds__(256) scatter_perm()
{
    const int t   = blockIdx.x * blockDim.x + threadIdx.x;
    const int qi0 = t * 4;

    const int4 vv = *(const int4*)(g_vidx + qi0);
    const int4 rr = *(const int4*)(g_rank + qi0);
    const int v[4] = {vv.x, vv.y, vv.z, vv.w};
    const int r[4] = {rr.x, rr.y, rr.z, rr.w};

    #pragma unroll
    for (int i = 0; i < 4; i++) {
        const int bin = (v[i] >= 0) ? (v[i] >> BUCKET_SHIFT) : (NBINS - 1);
        const int pos = __ldg(&g_off[bin]) + r[i];   // off[] is L2-resident
        g_perm[pos] = qi0 + i;
    }
}

__global__ void __launch_bounds__(THREADS) gather_phase(
    const float4* __restrict__ voxel_features,  // [total_voxels, 192] as float4
    float4* __restrict__ out)                   // [M, 192] as float4
{
    const int warp = threadIdx.x >> 5;
    const int lane = threadIdx.x & 31;
    const int wi   = blockIdx.x * (THREADS / 32) + warp;

    const int qi = __ldg(&g_perm[wi]);   // L2-resident, warp-broadcast
    const int v  = __ldg(&g_vidx[qi]);

    const float4* src = voxel_features + (size_t)v * VEC4_PER_ROW + lane;
    float4*       dst = out            + (size_t)qi * VEC4_PER_ROW + lane;

    float4 r[V4_PER_LANE];
    if (v >= 0) {
        #pragma unroll
        for (int i = 0; i < V4_PER_LANE; i++)   // 6 loads in flight (MLP=6)
            r[i] = __ldg(src + 32 * i);
    } else {
        #pragma unroll
        for (int i = 0; i < V4_PER_LANE; i++)
            r[i] = make_float4(0.f, 0.f, 0.f, 0.f);
    }

    // Streaming stores: output never re-read; keep L2 for feature rows.
    #pragma unroll
    for (int i = 0; i < V4_PER_LANE; i++)
        __stcs(dst + 32 * i, r[i]);
}

extern "C" void kernel_launch(void* const* d_in, const int* in_sizes, int n_in,
                              void* d_out, int out_size)
{
    const float*  query_pts = (const float*)d_in[0];
    const float4* feats     = (const float4*)d_in[1];
    const int*    buf       = (const int*)d_in[2];
    float4*       out       = (float4*)d_out;

    const int M = in_sizes[0] / 3;                  // 262144
    const int total_voxels = in_sizes[1] / FEATURE_DIM;

    zero_hist<<<NBINS / 1024, 1024>>>();
    hash_hist<<<M / (256 * 4), 256>>>(query_pts, buf, total_voxels);
    scan_hist<<<1, 1024>>>();
    scatter_perm<<<M / (256 * 4), 256>>>();

    gather_phase<<<M / (THREADS / 32), THREADS>>>(feats, out);
}